// round 1
// baseline (speedup 1.0000x reference)
#include <cuda_runtime.h>
#include <math.h>

#define BB 2
#define LL 2048
#define DD 256
#define HH 8
#define HD 32
#define BH (BB*HH)

// ---------------- scratch (device globals; no allocation allowed) ----------
__device__ float g_Q[(size_t)BB*HH*LL*HD];     // 4 MB  [b,h,l,d]
__device__ float g_K[(size_t)BB*HH*LL*HD];     // 4 MB
__device__ float g_V[(size_t)BB*HH*LL*HD];     // 4 MB
__device__ float g_O[(size_t)BB*HH*LL*HD];     // 4 MB  attn@V heads
__device__ float g_S[(size_t)BB*HH*LL*LL];     // 268 MB scores / attn
__device__ float g_E[HH*LL];                   // prior exp table per head
__device__ float g_rs[HH*LL];                  // prior row sums
__device__ float g_dpart[(size_t)BB*16*LL];    // discrepancy partials

// ---------------- helpers --------------------------------------------------
__device__ __forceinline__ float warpMax(float v){
    #pragma unroll
    for (int o=16;o;o>>=1) v = fmaxf(v, __shfl_xor_sync(0xffffffffu, v, o));
    return v;
}
__device__ __forceinline__ float warpSum(float v){
    #pragma unroll
    for (int o=16;o;o>>=1) v += __shfl_xor_sync(0xffffffffu, v, o);
    return v;
}

// ---------------- kernel 1: QKV projection --------------------------------
// C[m,n] = sum_k x[m,k]*W[n,k] + b[n], written in head-major layout.
__global__ __launch_bounds__(256) void qkv_kernel(
    const float* __restrict__ x,
    const float* __restrict__ Wq, const float* __restrict__ bq,
    const float* __restrict__ Wk, const float* __restrict__ bk,
    const float* __restrict__ Wv, const float* __restrict__ bv)
{
    __shared__ float Xs[64][33];
    __shared__ float Ws[64][33];
    const float* Wm; const float* bm; float* outp;
    if (blockIdx.z == 0)      { Wm=Wq; bm=bq; outp=g_Q; }
    else if (blockIdx.z == 1) { Wm=Wk; bm=bk; outp=g_K; }
    else                      { Wm=Wv; bm=bv; outp=g_V; }

    const int m0 = blockIdx.y*64, n0 = blockIdx.x*64;
    const int tid = threadIdx.x, tx = tid & 15, ty = tid >> 4;
    float acc[4][4] = {};

    for (int k0 = 0; k0 < DD; k0 += 32) {
        for (int idx = tid; idx < 2048; idx += 256) {
            int r = idx >> 5, c = idx & 31;
            Xs[r][c] = x[(size_t)(m0+r)*DD + k0 + c];
            Ws[r][c] = Wm[(size_t)(n0+r)*DD + k0 + c];
        }
        __syncthreads();
        #pragma unroll
        for (int kk = 0; kk < 32; kk++) {
            float a[4], w[4];
            #pragma unroll
            for (int i=0;i<4;i++) a[i] = Xs[ty*4+i][kk];
            #pragma unroll
            for (int j=0;j<4;j++) w[j] = Ws[tx*4+j][kk];
            #pragma unroll
            for (int i=0;i<4;i++)
                #pragma unroll
                for (int j=0;j<4;j++) acc[i][j] += a[i]*w[j];
        }
        __syncthreads();
    }
    #pragma unroll
    for (int i=0;i<4;i++){
        int m = m0 + ty*4 + i;
        int b = m >> 11, l = m & (LL-1);
        #pragma unroll
        for (int j=0;j<4;j++){
            int n = n0 + tx*4 + j;
            int h = n >> 5, d = n & 31;
            outp[(((size_t)(b*HH + h))*LL + l)*HD + d] = acc[i][j] + bm[n];
        }
    }
}

// ---------------- kernel 2a: prior exp table -------------------------------
__global__ void prior_e_kernel(const float* __restrict__ u)
{
    int h = blockIdx.x;
    float uv = u[h];
    float c = 0.5f / (uv*uv + 1e-6f);
    for (int d = threadIdx.x; d < LL; d += blockDim.x) {
        float fd = (float)d;
        g_E[h*LL + d] = expf(-(fd*fd) * c);
    }
}

// ---------------- kernel 2b: prior row sums --------------------------------
__global__ __launch_bounds__(256) void prior_rs_kernel()
{
    __shared__ float Es[LL];
    int h = blockIdx.y;
    for (int i = threadIdx.x; i < LL; i += 256) Es[i] = g_E[h*LL + i];
    __syncthreads();
    int q = blockIdx.x*256 + threadIdx.x;
    float s = 0.f;
    for (int k = 0; k < LL; k++) s += Es[abs(q - k)];
    g_rs[h*LL + q] = s;
}

// ---------------- kernel 3: scores = Q K^T / sqrt(hd) ----------------------
__global__ __launch_bounds__(256) void scores_kernel()
{
    __shared__ float Qs[64][33];
    __shared__ float Ks[64][33];
    const int bh = blockIdx.z;
    const float* Qp = g_Q + (size_t)bh*LL*HD;
    const float* Kp = g_K + (size_t)bh*LL*HD;
    float* Sp = g_S + (size_t)bh*LL*LL;

    const int q0 = blockIdx.y*64, k0 = blockIdx.x*64;
    const int tid = threadIdx.x, tx = tid & 15, ty = tid >> 4;

    for (int idx = tid; idx < 2048; idx += 256) {
        int r = idx >> 5, c = idx & 31;
        Qs[r][c] = Qp[(size_t)(q0+r)*HD + c];
        Ks[r][c] = Kp[(size_t)(k0+r)*HD + c];
    }
    __syncthreads();

    float acc[4][4] = {};
    #pragma unroll
    for (int kk = 0; kk < 32; kk++) {
        float a[4], w[4];
        #pragma unroll
        for (int i=0;i<4;i++) a[i] = Qs[ty*4+i][kk];
        #pragma unroll
        for (int j=0;j<4;j++) w[j] = Ks[tx*4+j][kk];
        #pragma unroll
        for (int i=0;i<4;i++)
            #pragma unroll
            for (int j=0;j<4;j++) acc[i][j] += a[i]*w[j];
    }
    const float scale = 0.17677669529663687f; // 1/sqrt(32)
    #pragma unroll
    for (int i=0;i<4;i++)
        #pragma unroll
        for (int j=0;j<4;j++)
            Sp[(size_t)(q0+ty*4+i)*LL + (k0+tx*4+j)] = acc[i][j]*scale;
}

// ---------------- kernel 4: row softmax, in place --------------------------
__global__ __launch_bounds__(256) void softmax_kernel()
{
    __shared__ float buf[LL];
    __shared__ float red[8];
    const size_t row = blockIdx.x;
    float* S = g_S + row*LL;
    const int tid = threadIdx.x;

    float m = -1e30f;
    for (int i = tid; i < LL; i += 256) { float v = S[i]; buf[i] = v; m = fmaxf(m, v); }
    m = warpMax(m);
    if ((tid & 31) == 0) red[tid >> 5] = m;
    __syncthreads();
    float tm = -1e30f;
    #pragma unroll
    for (int i=0;i<8;i++) tm = fmaxf(tm, red[i]);
    __syncthreads();

    float s = 0.f;
    for (int i = tid; i < LL; i += 256) { float e = __expf(buf[i] - tm); buf[i] = e; s += e; }
    s = warpSum(s);
    if ((tid & 31) == 0) red[tid >> 5] = s;
    __syncthreads();
    float ts = 0.f;
    #pragma unroll
    for (int i=0;i<8;i++) ts += red[i];
    float inv = 1.0f / ts;
    for (int i = tid; i < LL; i += 256) S[i] = buf[i]*inv;
}

// ---------------- kernel 5: discrepancy partials ---------------------------
// grid (L/256, 16 q-chunks, B); thread owns one (b,k); loops h and q-chunk.
__global__ __launch_bounds__(256) void disc_kernel()
{
    __shared__ float Es[LL];
    const int k  = blockIdx.x*256 + threadIdx.x;
    const int qc = blockIdx.y;
    const int b  = blockIdx.z;
    const int q0 = qc*128;
    float acc = 0.f;

    for (int h = 0; h < HH; h++) {
        __syncthreads();
        for (int i = threadIdx.x; i < LL; i += 256) Es[i] = g_E[h*LL + i];
        __syncthreads();
        const float* Sp = g_S + ((size_t)(b*HH + h))*LL*LL;
        const float* rs = g_rs + h*LL;
        #pragma unroll 4
        for (int q = q0; q < q0 + 128; q++) {
            float invr = 1.0f / (rs[q] + 1e-6f);
            float pr = Es[abs(q - k)] * invr;
            acc += fabsf(Sp[(size_t)q*LL + k] - pr);
        }
    }
    g_dpart[((size_t)b*16 + qc)*LL + k] = acc;
}

__global__ void disc_reduce_kernel(float* __restrict__ dout)
{
    int idx = blockIdx.x*256 + threadIdx.x;   // < B*L
    int b = idx >> 11, k = idx & (LL-1);
    float s = 0.f;
    #pragma unroll
    for (int c = 0; c < 16; c++) s += g_dpart[((size_t)b*16 + c)*LL + k];
    dout[idx] = s * (1.0f/(HH*(float)LL));
}

// ---------------- kernel 6: O = attn @ V -----------------------------------
__global__ __launch_bounds__(256) void av_kernel()
{
    __shared__ float As[128][33];   // 128 q rows x 32 k
    __shared__ float Vs[32][33];
    const int bh = blockIdx.y;
    const int q0 = blockIdx.x*128;
    const float* A = g_S + (size_t)bh*LL*LL;
    const float* V = g_V + (size_t)bh*LL*HD;
    const int tid = threadIdx.x, tx = tid & 31, ty = tid >> 5;  // ty: 0..7

    float acc[16] = {};
    for (int kt = 0; kt < LL/32; kt++) {
        for (int idx = tid; idx < 4096; idx += 256) {
            int r = idx >> 5, c = idx & 31;
            As[r][c] = A[(size_t)(q0+r)*LL + kt*32 + c];
        }
        for (int idx = tid; idx < 1024; idx += 256) {
            int r = idx >> 5, c = idx & 31;
            Vs[r][c] = V[(size_t)(kt*32 + r)*HD + c];
        }
        __syncthreads();
        #pragma unroll
        for (int kk = 0; kk < 32; kk++) {
            float v = Vs[kk][tx];
            #pragma unroll
            for (int r = 0; r < 16; r++) acc[r] += As[ty*16 + r][kk] * v;
        }
        __syncthreads();
    }
    #pragma unroll
    for (int r = 0; r < 16; r++)
        g_O[(size_t)bh*LL*HD + (size_t)(q0 + ty*16 + r)*HD + tx] = acc[r];
}

// ---------------- kernel 7: out projection ---------------------------------
__global__ __launch_bounds__(256) void outproj_kernel(
    const float* __restrict__ Wo, const float* __restrict__ bo,
    float* __restrict__ out)
{
    __shared__ float Xs[64][33];
    __shared__ float Ws[64][33];
    const int m0 = blockIdx.y*64, n0 = blockIdx.x*64;
    const int tid = threadIdx.x, tx = tid & 15, ty = tid >> 4;
    float acc[4][4] = {};

    for (int k0 = 0; k0 < DD; k0 += 32) {
        int h = k0 >> 5;
        for (int idx = tid; idx < 2048; idx += 256) {
            int r = idx >> 5, c = idx & 31;
            int m = m0 + r;
            int b = m >> 11, l = m & (LL-1);
            Xs[r][c] = g_O[(((size_t)(b*HH + h))*LL + l)*HD + c];
            Ws[r][c] = Wo[(size_t)(n0+r)*DD + k0 + c];
        }
        __syncthreads();
        #pragma unroll
        for (int kk = 0; kk < 32; kk++) {
            float a[4], w[4];
            #pragma unroll
            for (int i=0;i<4;i++) a[i] = Xs[ty*4+i][kk];
            #pragma unroll
            for (int j=0;j<4;j++) w[j] = Ws[tx*4+j][kk];
            #pragma unroll
            for (int i=0;i<4;i++)
                #pragma unroll
                for (int j=0;j<4;j++) acc[i][j] += a[i]*w[j];
        }
        __syncthreads();
    }
    #pragma unroll
    for (int i=0;i<4;i++){
        int m = m0 + ty*4 + i;
        #pragma unroll
        for (int j=0;j<4;j++){
            int n = n0 + tx*4 + j;
            out[(size_t)m*DD + n] = acc[i][j] + bo[n];
        }
    }
}

// ---------------- launch ---------------------------------------------------
extern "C" void kernel_launch(void* const* d_in, const int* in_sizes, int n_in,
                              void* d_out, int out_size)
{
    const float* x  = (const float*)d_in[0];
    const float* Wq = (const float*)d_in[1];
    const float* bq = (const float*)d_in[2];
    const float* Wk = (const float*)d_in[3];
    const float* bk = (const float*)d_in[4];
    const float* Wv = (const float*)d_in[5];
    const float* bv = (const float*)d_in[6];
    const float* u  = (const float*)d_in[7];
    const float* Wo = (const float*)d_in[8];
    const float* bo = (const float*)d_in[9];
    float* out = (float*)d_out;

    qkv_kernel<<<dim3(DD/64, (BB*LL)/64, 3), 256>>>(x, Wq, bq, Wk, bk, Wv, bv);
    prior_e_kernel<<<HH, 256>>>(u);
    prior_rs_kernel<<<dim3(LL/256, HH), 256>>>();
    scores_kernel<<<dim3(LL/64, LL/64, BH), 256>>>();
    softmax_kernel<<<BH*LL, 256>>>();
    disc_kernel<<<dim3(LL/256, 16, BB), 256>>>();
    disc_reduce_kernel<<<(BB*LL)/256, 256>>>(out + (size_t)BB*LL*DD);
    av_kernel<<<dim3(LL/128, BH), 256>>>();
    outproj_kernel<<<dim3(DD/64, (BB*LL)/64), 256>>>(Wo, bo, out);
}

// round 2
// speedup vs baseline: 2.1115x; 2.1115x over previous
#include <cuda_runtime.h>
#include <math.h>

#define BB 2
#define LL 2048
#define DD 256
#define HH 8
#define HD 32
#define BH (BB*HH)
#define QT 16          // q-rows per block in fused kernel
#define KCH 256        // k chunk in fused kernel

// ---------------- scratch (device globals; no allocation allowed) ----------
__device__ float g_Q[(size_t)BB*HH*LL*HD];     // 4 MB  [b,h,l,d]
__device__ float g_K[(size_t)BB*HH*LL*HD];     // 4 MB
__device__ float g_V[(size_t)BB*HH*LL*HD];     // 4 MB
__device__ float g_O[(size_t)BB*HH*LL*HD];     // 4 MB  attn@V heads
__device__ float g_S[(size_t)BB*HH*LL*LL];     // 268 MB normalized attn
__device__ float g_E[HH*LL];                   // prior exp table per head
__device__ float g_rs[HH*LL];                  // prior row sums
__device__ float g_dpart[(size_t)BB*HH*128*LL];// 16.8MB discrepancy partials

// ---------------- helpers --------------------------------------------------
__device__ __forceinline__ float warpMax(float v){
    #pragma unroll
    for (int o=16;o;o>>=1) v = fmaxf(v, __shfl_xor_sync(0xffffffffu, v, o));
    return v;
}
__device__ __forceinline__ float warpSum(float v){
    #pragma unroll
    for (int o=16;o;o>>=1) v += __shfl_xor_sync(0xffffffffu, v, o);
    return v;
}

// ---------------- kernel 1: QKV projection --------------------------------
__global__ __launch_bounds__(256) void qkv_kernel(
    const float* __restrict__ x,
    const float* __restrict__ Wq, const float* __restrict__ bq,
    const float* __restrict__ Wk, const float* __restrict__ bk,
    const float* __restrict__ Wv, const float* __restrict__ bv)
{
    __shared__ float Xs[64][33];
    __shared__ float Ws[64][33];
    const float* Wm; const float* bm; float* outp;
    if (blockIdx.z == 0)      { Wm=Wq; bm=bq; outp=g_Q; }
    else if (blockIdx.z == 1) { Wm=Wk; bm=bk; outp=g_K; }
    else                      { Wm=Wv; bm=bv; outp=g_V; }

    const int m0 = blockIdx.y*64, n0 = blockIdx.x*64;
    const int tid = threadIdx.x, tx = tid & 15, ty = tid >> 4;
    float acc[4][4] = {};

    for (int k0 = 0; k0 < DD; k0 += 32) {
        for (int idx = tid; idx < 2048; idx += 256) {
            int r = idx >> 5, c = idx & 31;
            Xs[r][c] = x[(size_t)(m0+r)*DD + k0 + c];
            Ws[r][c] = Wm[(size_t)(n0+r)*DD + k0 + c];
        }
        __syncthreads();
        #pragma unroll
        for (int kk = 0; kk < 32; kk++) {
            float a[4], w[4];
            #pragma unroll
            for (int i=0;i<4;i++) a[i] = Xs[ty*4+i][kk];
            #pragma unroll
            for (int j=0;j<4;j++) w[j] = Ws[tx*4+j][kk];
            #pragma unroll
            for (int i=0;i<4;i++)
                #pragma unroll
                for (int j=0;j<4;j++) acc[i][j] += a[i]*w[j];
        }
        __syncthreads();
    }
    #pragma unroll
    for (int i=0;i<4;i++){
        int m = m0 + ty*4 + i;
        int b = m >> 11, l = m & (LL-1);
        #pragma unroll
        for (int j=0;j<4;j++){
            int n = n0 + tx*4 + j;
            int h = n >> 5, d = n & 31;
            outp[(((size_t)(b*HH + h))*LL + l)*HD + d] = acc[i][j] + bm[n];
        }
    }
}

// ---------------- kernel 2a: prior exp table -------------------------------
__global__ void prior_e_kernel(const float* __restrict__ u)
{
    int h = blockIdx.x;
    float uv = u[h];
    float c = 0.5f / (uv*uv + 1e-6f);
    for (int d = threadIdx.x; d < LL; d += blockDim.x) {
        float fd = (float)d;
        g_E[h*LL + d] = expf(-(fd*fd) * c);
    }
}

// ---------------- kernel 2b: prior row sums --------------------------------
__global__ __launch_bounds__(256) void prior_rs_kernel()
{
    __shared__ float Es[LL];
    int h = blockIdx.y;
    for (int i = threadIdx.x; i < LL; i += 256) Es[i] = g_E[h*LL + i];
    __syncthreads();
    int q = blockIdx.x*256 + threadIdx.x;
    float s = 0.f;
    for (int k = 0; k < LL; k++) s += Es[abs(q - k)];
    g_rs[h*LL + q] = s;
}

// ---------------- kernel 3: FUSED scores+softmax+disc+attn-write -----------
// Block owns (bh, 16 q-rows). Full 16x2048 score strip lives in SMEM.
// Dynamic smem layout (floats):
//   Srow[16*2048] | Ks[256*33] | Qs[16*33] | Es[2048] | inv[16] | irs[16]
#define SM_SROW 0
#define SM_KS   (QT*LL)                 // 32768
#define SM_QS   (SM_KS + KCH*33)        // +8448
#define SM_ES   (SM_QS + QT*33)         // +528
#define SM_INV  (SM_ES + LL)            // +2048
#define SM_IRS  (SM_INV + QT)           // +16
#define SM_TOTF (SM_IRS + QT)           // total floats
#define SM_BYTES (SM_TOTF*4)

__global__ __launch_bounds__(256,1) void attn_row_kernel()
{
    extern __shared__ float sm[];
    float* Srow = sm + SM_SROW;
    float* Ks   = sm + SM_KS;
    float* Qs   = sm + SM_QS;
    float* Es   = sm + SM_ES;
    float* inv  = sm + SM_INV;
    float* irs  = sm + SM_IRS;

    const int tid = threadIdx.x;
    const int qt  = blockIdx.x;
    const int bh  = blockIdx.y;
    const int b   = bh >> 3, h = bh & 7;
    const int q0  = qt * QT;
    const float SCALE = 0.17677669529663687f;  // 1/sqrt(32)

    const float* Qp = g_Q + (size_t)bh*LL*HD;
    const float* Kp = g_K + (size_t)bh*LL*HD;

    // ---- phase 0: load Q tile (scaled), E table, inv row sums -------------
    for (int idx = tid; idx < QT*HD; idx += 256) {
        int r = idx >> 5, d = idx & 31;
        Qs[r*33 + d] = Qp[(size_t)(q0+r)*HD + d] * SCALE;
    }
    for (int idx = tid; idx < LL; idx += 256) Es[idx] = g_E[h*LL + idx];
    if (tid < QT) irs[tid] = 1.0f / (g_rs[h*LL + q0 + tid] + 1e-6f);

    // ---- phase 1: scores, chunked over k, K double-buffered in regs -------
    const float4* Kp4 = (const float4*)Kp;
    const int tx = tid & 63, ty = tid >> 6;
    float4 pre[8];
    #pragma unroll
    for (int t = 0; t < 8; t++) pre[t] = Kp4[tid + t*256];

    for (int kc = 0; kc < LL/KCH; kc++) {
        // store prefetched chunk into SMEM (conflict-free pattern)
        #pragma unroll
        for (int t = 0; t < 8; t++) {
            int f4 = tid + t*256;
            int r = f4 >> 3, c4 = f4 & 7;
            float* p = &Ks[r*33 + c4*4];
            p[0]=pre[t].x; p[1]=pre[t].y; p[2]=pre[t].z; p[3]=pre[t].w;
        }
        __syncthreads();
        if (kc < LL/KCH - 1) {
            #pragma unroll
            for (int t = 0; t < 8; t++)
                pre[t] = Kp4[(kc+1)*(KCH*HD/4) + tid + t*256];
        }
        float acc[4][4] = {};
        #pragma unroll
        for (int kk = 0; kk < 32; kk++) {
            float a[4], bv[4];
            #pragma unroll
            for (int i=0;i<4;i++) a[i]  = Qs[(ty + 4*i)*33 + kk];
            #pragma unroll
            for (int j=0;j<4;j++) bv[j] = Ks[(tx + 64*j)*33 + kk];
            #pragma unroll
            for (int i=0;i<4;i++)
                #pragma unroll
                for (int j=0;j<4;j++) acc[i][j] += a[i]*bv[j];
        }
        #pragma unroll
        for (int i=0;i<4;i++)
            #pragma unroll
            for (int j=0;j<4;j++)
                Srow[(ty + 4*i)*LL + kc*KCH + tx + 64*j] = acc[i][j];
        __syncthreads();
    }

    // ---- phase 2: rowmax, exp, rowsum (warp per 2 rows) -------------------
    const int wid = tid >> 5, lane = tid & 31;
    #pragma unroll
    for (int rr = 0; rr < 2; rr++) {
        int r = wid*2 + rr;
        float m = -3.4e38f;
        for (int k = lane; k < LL; k += 32) m = fmaxf(m, Srow[r*LL + k]);
        m = warpMax(m);
        float s = 0.f;
        for (int k = lane; k < LL; k += 32) {
            float e = __expf(Srow[r*LL + k] - m);
            Srow[r*LL + k] = e;
            s += e;
        }
        s = warpSum(s);
        if (lane == 0) inv[r] = 1.0f / s;
    }
    __syncthreads();

    // ---- phase 3: discrepancy partials (per k column over 16 q) -----------
    {
        size_t pbase = (((size_t)(b*HH + h))*128 + qt) * LL;
        #pragma unroll
        for (int t = 0; t < 8; t++) {
            int k = tid + t*256;
            float acc = 0.f;
            #pragma unroll
            for (int q = 0; q < QT; q++) {
                float a = Srow[q*LL + k] * inv[q];
                float p = Es[abs(q0 + q - k)] * irs[q];
                acc += fabsf(a - p);
            }
            g_dpart[pbase + k] = acc;
        }
    }

    // ---- phase 4: write normalized attn (vectorized) ----------------------
    {
        float4* Sg4 = (float4*)(g_S + ((size_t)bh*LL + q0)*LL);
        #pragma unroll
        for (int t = 0; t < 32; t++) {
            int idx = tid + t*256;        // f4 index within 16x512
            int r = idx >> 9, c4 = idx & 511;
            float4 v = *(float4*)&Srow[r*LL + c4*4];
            float iv = inv[r];
            v.x *= iv; v.y *= iv; v.z *= iv; v.w *= iv;
            Sg4[(size_t)r*(LL/4) + c4] = v;
        }
    }
}

// ---------------- kernel 4: discrepancy reduce -----------------------------
__global__ void disc_reduce_kernel(float* __restrict__ dout)
{
    int idx = blockIdx.x*256 + threadIdx.x;   // < B*L
    int b = idx >> 11, k = idx & (LL-1);
    float s = 0.f;
    const float* base = g_dpart + (size_t)b*HH*128*LL + k;
    for (int p = 0; p < HH*128; p++) s += base[(size_t)p*LL];
    dout[idx] = s * (1.0f/(HH*(float)LL));
}

// ---------------- kernel 5: O = attn @ V (register-blocked GEMM) -----------
// block: 64 q x 32 d, 128 threads, per-thread 4q x 4d, k-chunks of 32
__global__ __launch_bounds__(128) void av_kernel()
{
    __shared__ float As[64][33];
    __shared__ float Vs[32][33];
    const int bh = blockIdx.y;
    const int q0 = blockIdx.x*64;
    const float* A = g_S + (size_t)bh*LL*LL;
    const float* V = g_V + (size_t)bh*LL*HD;
    const int tid = threadIdx.x, tx = tid & 7, ty = tid >> 3;  // ty 0..15

    float acc[4][4] = {};
    for (int k0 = 0; k0 < LL; k0 += 32) {
        #pragma unroll
        for (int t = 0; t < 16; t++) {
            int idx = tid + t*128;
            int r = idx >> 5, c = idx & 31;
            As[r][c] = A[(size_t)(q0+r)*LL + k0 + c];
        }
        #pragma unroll
        for (int t = 0; t < 8; t++) {
            int idx = tid + t*128;
            int r = idx >> 5, c = idx & 31;
            Vs[r][c] = V[(size_t)(k0+r)*HD + c];
        }
        __syncthreads();
        #pragma unroll
        for (int kk = 0; kk < 32; kk++) {
            float a[4], bv[4];
            #pragma unroll
            for (int i=0;i<4;i++) a[i]  = As[ty + 16*i][kk];
            #pragma unroll
            for (int j=0;j<4;j++) bv[j] = Vs[kk][tx + 8*j];
            #pragma unroll
            for (int i=0;i<4;i++)
                #pragma unroll
                for (int j=0;j<4;j++) acc[i][j] += a[i]*bv[j];
        }
        __syncthreads();
    }
    #pragma unroll
    for (int i=0;i<4;i++)
        #pragma unroll
        for (int j=0;j<4;j++)
            g_O[((size_t)bh*LL + q0 + ty + 16*i)*HD + tx + 8*j] = acc[i][j];
}

// ---------------- kernel 6: out projection ---------------------------------
__global__ __launch_bounds__(256) void outproj_kernel(
    const float* __restrict__ Wo, const float* __restrict__ bo,
    float* __restrict__ out)
{
    __shared__ float Xs[64][33];
    __shared__ float Ws[64][33];
    const int m0 = blockIdx.y*64, n0 = blockIdx.x*64;
    const int tid = threadIdx.x, tx = tid & 15, ty = tid >> 4;
    float acc[4][4] = {};

    for (int k0 = 0; k0 < DD; k0 += 32) {
        int h = k0 >> 5;
        for (int idx = tid; idx < 2048; idx += 256) {
            int r = idx >> 5, c = idx & 31;
            int m = m0 + r;
            int b = m >> 11, l = m & (LL-1);
            Xs[r][c] = g_O[(((size_t)(b*HH + h))*LL + l)*HD + c];
            Ws[r][c] = Wo[(size_t)(n0+r)*DD + k0 + c];
        }
        __syncthreads();
        #pragma unroll
        for (int kk = 0; kk < 32; kk++) {
            float a[4], w[4];
            #pragma unroll
            for (int i=0;i<4;i++) a[i] = Xs[ty*4+i][kk];
            #pragma unroll
            for (int j=0;j<4;j++) w[j] = Ws[tx*4+j][kk];
            #pragma unroll
            for (int i=0;i<4;i++)
                #pragma unroll
                for (int j=0;j<4;j++) acc[i][j] += a[i]*w[j];
        }
        __syncthreads();
    }
    #pragma unroll
    for (int i=0;i<4;i++){
        int m = m0 + ty*4 + i;
        #pragma unroll
        for (int j=0;j<4;j++){
            int n = n0 + tx*4 + j;
            out[(size_t)m*DD + n] = acc[i][j] + bo[n];
        }
    }
}

// ---------------- launch ---------------------------------------------------
extern "C" void kernel_launch(void* const* d_in, const int* in_sizes, int n_in,
                              void* d_out, int out_size)
{
    const float* x  = (const float*)d_in[0];
    const float* Wq = (const float*)d_in[1];
    const float* bq = (const float*)d_in[2];
    const float* Wk = (const float*)d_in[3];
    const float* bk = (const float*)d_in[4];
    const float* Wv = (const float*)d_in[5];
    const float* bv = (const float*)d_in[6];
    const float* u  = (const float*)d_in[7];
    const float* Wo = (const float*)d_in[8];
    const float* bo = (const float*)d_in[9];
    float* out = (float*)d_out;

    cudaFuncSetAttribute(attn_row_kernel,
                         cudaFuncAttributeMaxDynamicSharedMemorySize, SM_BYTES);

    qkv_kernel<<<dim3(DD/64, (BB*LL)/64, 3), 256>>>(x, Wq, bq, Wk, bk, Wv, bv);
    prior_e_kernel<<<HH, 256>>>(u);
    prior_rs_kernel<<<dim3(LL/256, HH), 256>>>();
    attn_row_kernel<<<dim3(LL/QT, BH), 256, SM_BYTES>>>();
    disc_reduce_kernel<<<(BB*LL)/256, 256>>>(out + (size_t)BB*LL*DD);
    av_kernel<<<dim3(LL/64, BH), 128>>>();
    outproj_kernel<<<dim3(DD/64, (BB*LL)/64), 256>>>(Wo, bo, out);
}